// round 10
// baseline (speedup 1.0000x reference)
#include <cuda_runtime.h>
#include <cuda_fp16.h>
#include <mma.h>
#include <math_constants.h>

using namespace nvcuda;

#define N_NODES 50000
#define N_EDGES 800000
#define IN_CH   64
#define HEADS   4
#define OUT_CH  64
#define HC      (HEADS * OUT_CH)   // 256
#define NEG_SLOPE 0.2f
#define NBLK_NODES 196             // ceil(50000/256)

#define GT_M    64                 // nodes per gemm block
#define W_COLS  272                // 256 xt cols + 8 logit cols + 8 pad
#define WS_LD   152                // smem slice leading dim (max 144 cols + 8 pad)
#define XA_LD   72                 // x tile leading dim (halves)
#define NBLK_GEMM ((N_NODES + GT_M - 1) / GT_M)   // 782

// ---------------- device scratch ----------------
__device__ __align__(16) __half2 g_xth[(size_t)N_NODES * (HC / 2)]; // [N,128] fp16x2
__device__ __align__(16) __half  g_Wh[64 * W_COLS];                 // W'' fp16
__device__ __align__(16) float g_asrc[N_NODES * HEADS];
__device__ __align__(16) float g_adst[N_NODES * HEADS];
__device__ int   g_count[N_NODES];
__device__ int   g_offs[N_NODES];
__device__ int   g_cursor[N_NODES];
__device__ int   g_esrc[N_EDGES];
__device__ int   g_bsum[256];
__device__ int   g_boff[256];

__device__ __forceinline__ float leaky(float v) {
    return (v > 0.0f) ? v : NEG_SLOPE * v;
}

// ---------------- K0: prep — zero counts + build fp16 W'' = [W | W@Vsrc | W@Vdst | 0]
__global__ void prep_kernel(const float* __restrict__ W,
                            const float* __restrict__ att_src,
                            const float* __restrict__ att_dst) {
    int i = blockIdx.x * blockDim.x + threadIdx.x;
    if (i < N_NODES) g_count[i] = 0;
    if (i < 64 * W_COLS) {
        int k = i / W_COLS, c = i % W_COLS;
        float v;
        if (c < HC) {
            v = W[(size_t)k * HC + c];
        } else if (c < HC + 8) {
            int h = (c - HC) & 3;
            const float* av = (c < HC + 4) ? att_src : att_dst;
            float s = 0.0f;
            for (int t = 0; t < OUT_CH; t++)
                s += W[(size_t)k * HC + h * OUT_CH + t] * av[h * OUT_CH + t];
            v = s;
        } else {
            v = 0.0f;
        }
        g_Wh[i] = __float2half(v);
    }
}

// ---------------- K1: xt = x @ W'' on fp16 HMMA, column-split over grid.y ------
// grid (782, 2). y=0: W'' cols [0,128) = 8 tiles; y=1: cols [128,272) = 9 tiles
// (tile 16 = logit cols). 8 warps = 4 node-tiles x 2 col-subranges.
// Dual accumulators; xa smem reused as epilogue stage after A-frags load.
__global__ void __launch_bounds__(256) gemm_kernel(const float* __restrict__ x) {
    __shared__ __align__(16) __half xa[GT_M * XA_LD];   // 9216 B; reused as stage
    __shared__ __align__(16) __half Ws[64 * WS_LD];     // 19456 B

    const int tid  = threadIdx.x;
    const int warp = tid >> 5;
    const int lane = tid & 31;
    const int nblk = blockIdx.x * GT_M;
    const int colbase = blockIdx.y * 128;              // in halves
    const int wcols   = blockIdx.y ? 144 : 128;        // slice width
    const int nlt     = wcols >> 4;                    // 8 or 9 local tiles

    // x tile [64 x 64] fp32 -> fp16 (zero-pad OOB)
    for (int i = tid; i < GT_M * IN_CH; i += 256) {
        int n = i >> 6, k = i & 63;
        int node = nblk + n;
        xa[n * XA_LD + k] = __float2half((node < N_NODES) ? x[(size_t)node * IN_CH + k] : 0.0f);
    }
    // W'' slice [64 x wcols] vectorized into smem
    for (int i = tid; i < 64 * (wcols >> 3); i += 256) {
        int k = i / (wcols >> 3), c8 = i % (wcols >> 3);
        *(uint4*)(Ws + k * WS_LD + c8 * 8) =
            __ldg((const uint4*)(g_Wh + (size_t)k * W_COLS + colbase) + c8);
    }
    __syncthreads();

    const int mw  = warp >> 1;         // node tile 0..3
    const int sub = warp & 1;
    const int lt_begin = sub ? 4 : 0;
    const int lt_end   = sub ? nlt : 4;

    wmma::fragment<wmma::matrix_a, 16, 16, 16, __half, wmma::row_major> af[4];
#pragma unroll
    for (int kk = 0; kk < 4; kk++)
        wmma::load_matrix_sync(af[kk], xa + (mw * 16) * XA_LD + kk * 16, XA_LD);
    __syncthreads();    // A-frags register-resident; xa becomes the stage

    float* st = (float*)xa + warp * (16 * 16);   // 1 KB per warp
    __half* xth = (__half*)g_xth;

    auto emit = [&](int lt, wmma::fragment<wmma::accumulator, 16, 16, 16, float>& acc) {
        int ct = (colbase >> 4) + lt;            // global col tile
        wmma::store_matrix_sync(st, acc, 16, wmma::mem_row_major);
        __syncwarp();
        if (ct < 16) {
            int row = lane & 15, ch = lane >> 4;
            int node = nblk + mw * 16 + row;
            if (node < N_NODES) {
                float4 u = *(const float4*)(st + row * 16 + ch * 8);
                float4 v = *(const float4*)(st + row * 16 + ch * 8 + 4);
                __half2 h0 = __floats2half2_rn(u.x, u.y);
                __half2 h1 = __floats2half2_rn(u.z, u.w);
                __half2 h2 = __floats2half2_rn(v.x, v.y);
                __half2 h3 = __floats2half2_rn(v.z, v.w);
                uint4 o = make_uint4(*(unsigned*)&h0, *(unsigned*)&h1,
                                     *(unsigned*)&h2, *(unsigned*)&h3);
                *(uint4*)(xth + (size_t)node * HC + ct * 16 + ch * 8) = o;
            }
        } else {
            if (lane < 16) {
                int node = nblk + mw * 16 + lane;
                if (node < N_NODES) {
                    *(float4*)(g_asrc + node * 4) = *(const float4*)(st + lane * 16);
                    *(float4*)(g_adst + node * 4) = *(const float4*)(st + lane * 16 + 4);
                }
            }
        }
        __syncwarp();
    };

    for (int lt = lt_begin; lt < lt_end; lt += 2) {
        bool has2 = (lt + 1) < lt_end;
        wmma::fragment<wmma::accumulator, 16, 16, 16, float> acc0, acc1;
        wmma::fill_fragment(acc0, 0.0f);
        if (has2) wmma::fill_fragment(acc1, 0.0f);
#pragma unroll
        for (int kk = 0; kk < 4; kk++) {
            wmma::fragment<wmma::matrix_b, 16, 16, 16, __half, wmma::row_major> b0, b1;
            wmma::load_matrix_sync(b0, Ws + (kk * 16) * WS_LD + lt * 16, WS_LD);
            if (has2) wmma::load_matrix_sync(b1, Ws + (kk * 16) * WS_LD + (lt + 1) * 16, WS_LD);
            wmma::mma_sync(acc0, af[kk], b0, acc0);
            if (has2) wmma::mma_sync(acc1, af[kk], b1, acc1);
        }
        emit(lt, acc0);
        if (has2) emit(lt + 1, acc1);
    }
}

// ---------------- CSR build ----------------
__global__ void count_kernel(const int* __restrict__ ei) {
    int i = blockIdx.x * blockDim.x + threadIdx.x;
    if (i < N_EDGES / 4) {
        int4 d = __ldg((const int4*)(ei + N_EDGES) + i);
        atomicAdd(&g_count[d.x], 1);
        atomicAdd(&g_count[d.y], 1);
        atomicAdd(&g_count[d.z], 1);
        atomicAdd(&g_count[d.w], 1);
    }
}

__global__ void scanA_kernel() {
    __shared__ int wsum[8];
    int i = blockIdx.x * 256 + threadIdx.x;
    int c = (i < N_NODES) ? g_count[i] : 0;
    int v = c;
#pragma unroll
    for (int off = 16; off > 0; off >>= 1)
        v += __shfl_down_sync(0xFFFFFFFFu, v, off);
    if ((threadIdx.x & 31) == 0) wsum[threadIdx.x >> 5] = v;
    __syncthreads();
    if (threadIdx.x == 0) {
        int s = 0;
#pragma unroll
        for (int w = 0; w < 8; w++) s += wsum[w];
        g_bsum[blockIdx.x] = s;
    }
}

__global__ void scanB_kernel() {
    __shared__ int sm[256];
    int t = threadIdx.x;
    int v = (t < NBLK_NODES) ? g_bsum[t] : 0;
    sm[t] = v;
    __syncthreads();
    for (int off = 1; off < 256; off <<= 1) {
        int u = (t >= off) ? sm[t - off] : 0;
        __syncthreads();
        sm[t] += u;
        __syncthreads();
    }
    if (t < NBLK_NODES) g_boff[t] = sm[t] - v;
}

__global__ void scanC_kernel() {
    __shared__ int sm[256];
    int t = threadIdx.x;
    int i = blockIdx.x * 256 + t;
    int c = (i < N_NODES) ? g_count[i] : 0;
    sm[t] = c;
    __syncthreads();
    for (int off = 1; off < 256; off <<= 1) {
        int u = (t >= off) ? sm[t - off] : 0;
        __syncthreads();
        sm[t] += u;
        __syncthreads();
    }
    if (i < N_NODES) {
        int off = g_boff[blockIdx.x] + sm[t] - c;
        g_offs[i] = off;
        g_cursor[i] = off;
    }
}

// ---------------- scatter: dst-sort edges only (weights computed in agg) ------
__global__ void scatter_kernel(const int* __restrict__ ei) {
    int i = blockIdx.x * blockDim.x + threadIdx.x;
    if (i < N_EDGES / 4) {
        int4 s4 = __ldg((const int4*)ei + i);
        int4 d4 = __ldg((const int4*)(ei + N_EDGES) + i);
        int p0 = atomicAdd(&g_cursor[d4.x], 1); g_esrc[p0] = s4.x;
        int p1 = atomicAdd(&g_cursor[d4.y], 1); g_esrc[p1] = s4.y;
        int p2 = atomicAdd(&g_cursor[d4.z], 1); g_esrc[p2] = s4.z;
        int p3 = atomicAdd(&g_cursor[d4.w], 1); g_esrc[p3] = s4.w;
    }
}

// ---------------- agg: gather + inline softmax weights + head-mean + relu + fc -
// one warp per dst node. lane owns bytes [16*lane,16*lane+16) of the 512B row:
// 8 channels of head (lane>>3), channel-in-head base cb=(lane&7)*8.
// w computed inline: exp(leaky(asrc[j][h] + adst[i][h])).
__global__ void agg_kernel(const float* __restrict__ bias,
                           const float* __restrict__ fc_w,
                           const float* __restrict__ fc_b,
                           float* __restrict__ out) {
    int i    = (blockIdx.x * blockDim.x + threadIdx.x) >> 5;
    int lane = threadIdx.x & 31;
    if (i >= N_NODES) return;

    const int h  = lane >> 3;
    const int cb = (lane & 7) * 8;
    const int start = g_offs[i];
    const int deg   = g_count[i];

    const float ad_h  = __ldg(g_adst + 4 * i + h);
    const float selfw = __expf(leaky(__ldg(g_asrc + 4 * i + h) + ad_h));

    float acc[8] = {0, 0, 0, 0, 0, 0, 0, 0};
    float s = 0.0f;

    int jn; float wn;
    if (deg > 0) {
        jn = __ldg(g_esrc + start);
        wn = __expf(leaky(__ldg(g_asrc + 4 * jn + h) + ad_h));
    } else {
        jn = i; wn = selfw;
    }

    for (int e = 0; e <= deg; e++) {
        int j = jn; float w = wn;
        int en = e + 1;
        if (en < deg) {
            jn = __ldg(g_esrc + start + en);
            wn = __expf(leaky(__ldg(g_asrc + 4 * jn + h) + ad_h));
        } else if (en == deg) {
            jn = i; wn = selfw;
        }

        s += w;
        uint4 v = __ldg((const uint4*)(g_xth + (size_t)j * (HC / 2)) + lane);
        float2 f0 = __half22float2(*(__half2*)&v.x);
        float2 f1 = __half22float2(*(__half2*)&v.y);
        float2 f2 = __half22float2(*(__half2*)&v.z);
        float2 f3 = __half22float2(*(__half2*)&v.w);
        acc[0] += w * f0.x; acc[1] += w * f0.y;
        acc[2] += w * f1.x; acc[3] += w * f1.y;
        acc[4] += w * f2.x; acc[5] += w * f2.y;
        acc[6] += w * f3.x; acc[7] += w * f3.y;
    }

    float inv = 0.25f / s;
#pragma unroll
    for (int c = 0; c < 8; c++) acc[c] *= inv;
#pragma unroll
    for (int c = 0; c < 8; c++) {
        acc[c] += __shfl_xor_sync(0xFFFFFFFFu, acc[c], 8);
        acc[c] += __shfl_xor_sync(0xFFFFFFFFu, acc[c], 16);
    }

    float4 b0 = __ldg((const float4*)(bias + cb));
    float4 b1 = __ldg((const float4*)(bias + cb + 4));
    float4 f0 = __ldg((const float4*)(fc_w + cb));
    float4 f1 = __ldg((const float4*)(fc_w + cb + 4));

    float p = fmaxf(acc[0] + b0.x, 0.0f) * f0.x
            + fmaxf(acc[1] + b0.y, 0.0f) * f0.y
            + fmaxf(acc[2] + b0.z, 0.0f) * f0.z
            + fmaxf(acc[3] + b0.w, 0.0f) * f0.w
            + fmaxf(acc[4] + b1.x, 0.0f) * f1.x
            + fmaxf(acc[5] + b1.y, 0.0f) * f1.y
            + fmaxf(acc[6] + b1.z, 0.0f) * f1.z
            + fmaxf(acc[7] + b1.w, 0.0f) * f1.w;

    p += __shfl_down_sync(0xFFFFFFFFu, p, 4, 8);
    p += __shfl_down_sync(0xFFFFFFFFu, p, 2, 8);
    p += __shfl_down_sync(0xFFFFFFFFu, p, 1, 8);

    if (lane == 0) out[i] = p + __ldg(fc_b);
}

// ---------------- launch ----------------
// gemm_kernel at launch index 3 (ncu capture slot) to verify the split.
extern "C" void kernel_launch(void* const* d_in, const int* in_sizes, int n_in,
                              void* d_out, int out_size) {
    const float* x        = (const float*)d_in[0];
    const int*   ei       = (const int*)d_in[1];     // int32 [2, E]
    const float* W        = (const float*)d_in[2];
    const float* att_src  = (const float*)d_in[3];
    const float* att_dst  = (const float*)d_in[4];
    const float* bias     = (const float*)d_in[5];
    const float* fc_w     = (const float*)d_in[6];
    const float* fc_b     = (const float*)d_in[7];
    float*       out      = (float*)d_out;

    (void)in_sizes; (void)n_in; (void)out_size;

    prep_kernel<<<NBLK_NODES, 256>>>(W, att_src, att_dst);
    count_kernel<<<(N_EDGES / 4 + 255) / 256, 256>>>(ei);
    scanA_kernel<<<NBLK_NODES, 256>>>();
    gemm_kernel<<<dim3(NBLK_GEMM, 2), 256>>>(x);               // capture slot
    scanB_kernel<<<1, 256>>>();
    scanC_kernel<<<NBLK_NODES, 256>>>();
    scatter_kernel<<<(N_EDGES / 4 + 255) / 256, 256>>>(ei);
    agg_kernel<<<(N_NODES * 32 + 255) / 256, 256>>>(bias, fc_w, fc_b, out);
}

// round 11
// speedup vs baseline: 1.0896x; 1.0896x over previous
#include <cuda_runtime.h>
#include <cuda_fp16.h>
#include <mma.h>
#include <math_constants.h>

using namespace nvcuda;

#define N_NODES 50000
#define N_EDGES 800000
#define IN_CH   64
#define HEADS   4
#define OUT_CH  64
#define HC      (HEADS * OUT_CH)   // 256
#define NEG_SLOPE 0.2f
#define NBLK_NODES 196             // ceil(50000/256)

#define GT_M    64                 // nodes per gemm block
#define W_COLS  272                // 256 xt cols + 8 logit cols + 8 pad
#define W_LD    280                // Ws smem leading dim (halves)
#define XA_LD   72                 // x tile leading dim (halves)
#define GEMM_THREADS 288           // 9 warps
#define NBLK_GEMM ((N_NODES + GT_M - 1) / GT_M)   // 782

// ---------------- device scratch ----------------
__device__ __align__(16) __half2 g_xth[(size_t)N_NODES * (HC / 2)]; // [N,128] fp16x2
__device__ __align__(16) __half  g_Wh[64 * W_COLS];                 // W'' fp16
__device__ __align__(16) float g_asrc[N_NODES * HEADS];
__device__ __align__(16) float g_adst[N_NODES * HEADS];
__device__ __align__(16) float4 g_w[N_EDGES];      // per-edge softmax numerators
__device__ int   g_count[N_NODES];
__device__ int   g_offs[N_NODES];
__device__ int   g_cursor[N_NODES];
__device__ int   g_esrc[N_EDGES];
__device__ int   g_bsum[256];
__device__ int   g_boff[256];

__device__ __forceinline__ float leaky(float v) {
    return (v > 0.0f) ? v : NEG_SLOPE * v;
}

// ---------------- K0: prep — zero counts + build fp16 W'' = [W | W@Vsrc | W@Vdst | 0]
__global__ void prep_kernel(const float* __restrict__ W,
                            const float* __restrict__ att_src,
                            const float* __restrict__ att_dst) {
    int i = blockIdx.x * blockDim.x + threadIdx.x;
    if (i < N_NODES) g_count[i] = 0;
    if (i < 64 * W_COLS) {
        int k = i / W_COLS, c = i % W_COLS;
        float v;
        if (c < HC) {
            v = W[(size_t)k * HC + c];
        } else if (c < HC + 8) {
            int h = (c - HC) & 3;
            const float* av = (c < HC + 4) ? att_src : att_dst;
            float s = 0.0f;
            for (int t = 0; t < OUT_CH; t++)
                s += W[(size_t)k * HC + h * OUT_CH + t] * av[h * OUT_CH + t];
            v = s;
        } else {
            v = 0.0f;
        }
        g_Wh[i] = __float2half(v);
    }
}

// ---------------- K1: xt = x @ W'' on fp16 HMMA, B fragments register-resident -
// 288 threads (9 warps). Warp w<8 owns col tiles {2w, 2w+1}; warp 8 owns the
// logit tile (16). Each warp loads its B-frags ONCE, then loops over the 4
// node tiles, loading A-frags per tile and running two interleaved MMA chains.
__global__ void __launch_bounds__(GEMM_THREADS) gemm_kernel(const float* __restrict__ x) {
    __shared__ __align__(16) __half xa[GT_M * XA_LD];      // 9216 B (persistent)
    __shared__ __align__(16) __half Ws[64 * W_LD];         // 35840 B
    __shared__ __align__(16) float  stage[9][16 * 16];     // 9216 B

    const int tid  = threadIdx.x;
    const int warp = tid >> 5;
    const int lane = tid & 31;
    const int nblk = blockIdx.x * GT_M;

    // x tile [64 x 64] fp32 -> fp16 (zero-pad OOB)
    for (int i = tid; i < GT_M * IN_CH; i += GEMM_THREADS) {
        int n = i >> 6, k = i & 63;
        int node = nblk + n;
        xa[n * XA_LD + k] = __float2half((node < N_NODES) ? x[(size_t)node * IN_CH + k] : 0.0f);
    }
    // W'' [64 x 272] vectorized into smem
    for (int i = tid; i < 64 * (W_COLS / 8); i += GEMM_THREADS) {
        int k = i / (W_COLS / 8), c8 = i % (W_COLS / 8);
        *(uint4*)(Ws + k * W_LD + c8 * 8) = __ldg((const uint4*)(g_Wh + k * W_COLS) + c8);
    }
    __syncthreads();

    const int  ct0  = (warp < 8) ? (2 * warp) : 16;
    const bool has2 = (warp < 8);
    const int  ct1  = ct0 + 1;

    // B fragments: register-resident for this warp's column tiles
    wmma::fragment<wmma::matrix_b, 16, 16, 16, __half, wmma::row_major> b0[4], b1[4];
#pragma unroll
    for (int kk = 0; kk < 4; kk++) {
        wmma::load_matrix_sync(b0[kk], Ws + (kk * 16) * W_LD + ct0 * 16, W_LD);
        if (has2) wmma::load_matrix_sync(b1[kk], Ws + (kk * 16) * W_LD + ct1 * 16, W_LD);
    }

    float* st = stage[warp];
    __half* xth = (__half*)g_xth;

    auto emit = [&](int nt, int ct, wmma::fragment<wmma::accumulator, 16, 16, 16, float>& acc) {
        wmma::store_matrix_sync(st, acc, 16, wmma::mem_row_major);
        __syncwarp();
        if (ct < 16) {
            int row = lane & 15, ch = lane >> 4;
            int node = nblk + nt * 16 + row;
            if (node < N_NODES) {
                float4 u = *(const float4*)(st + row * 16 + ch * 8);
                float4 v = *(const float4*)(st + row * 16 + ch * 8 + 4);
                __half2 h0 = __floats2half2_rn(u.x, u.y);
                __half2 h1 = __floats2half2_rn(u.z, u.w);
                __half2 h2 = __floats2half2_rn(v.x, v.y);
                __half2 h3 = __floats2half2_rn(v.z, v.w);
                uint4 o = make_uint4(*(unsigned*)&h0, *(unsigned*)&h1,
                                     *(unsigned*)&h2, *(unsigned*)&h3);
                *(uint4*)(xth + (size_t)node * HC + ct * 16 + ch * 8) = o;
            }
        } else {
            if (lane < 16) {
                int node = nblk + nt * 16 + lane;
                if (node < N_NODES) {
                    *(float4*)(g_asrc + node * 4) = *(const float4*)(st + lane * 16);
                    *(float4*)(g_adst + node * 4) = *(const float4*)(st + lane * 16 + 4);
                }
            }
        }
        __syncwarp();
    };

    // loop over 4 node tiles; two independent MMA chains per iteration
#pragma unroll
    for (int nt = 0; nt < 4; nt++) {
        wmma::fragment<wmma::matrix_a, 16, 16, 16, __half, wmma::row_major> af;
        wmma::fragment<wmma::accumulator, 16, 16, 16, float> acc0, acc1;
        wmma::fill_fragment(acc0, 0.0f);
        if (has2) wmma::fill_fragment(acc1, 0.0f);
#pragma unroll
        for (int kk = 0; kk < 4; kk++) {
            wmma::load_matrix_sync(af, xa + (nt * 16) * XA_LD + kk * 16, XA_LD);
            wmma::mma_sync(acc0, af, b0[kk], acc0);
            if (has2) wmma::mma_sync(acc1, af, b1[kk], acc1);
        }
        emit(nt, ct0, acc0);
        if (has2) emit(nt, ct1, acc1);
    }
}

// ---------------- CSR build ----------------
__global__ void count_kernel(const int* __restrict__ ei) {
    int i = blockIdx.x * blockDim.x + threadIdx.x;
    if (i < N_EDGES / 4) {
        int4 d = __ldg((const int4*)(ei + N_EDGES) + i);
        atomicAdd(&g_count[d.x], 1);
        atomicAdd(&g_count[d.y], 1);
        atomicAdd(&g_count[d.z], 1);
        atomicAdd(&g_count[d.w], 1);
    }
}

__global__ void scanA_kernel() {
    __shared__ int wsum[8];
    int i = blockIdx.x * 256 + threadIdx.x;
    int c = (i < N_NODES) ? g_count[i] : 0;
    int v = c;
#pragma unroll
    for (int off = 16; off > 0; off >>= 1)
        v += __shfl_down_sync(0xFFFFFFFFu, v, off);
    if ((threadIdx.x & 31) == 0) wsum[threadIdx.x >> 5] = v;
    __syncthreads();
    if (threadIdx.x == 0) {
        int s = 0;
#pragma unroll
        for (int w = 0; w < 8; w++) s += wsum[w];
        g_bsum[blockIdx.x] = s;
    }
}

__global__ void scanB_kernel() {
    __shared__ int sm[256];
    int t = threadIdx.x;
    int v = (t < NBLK_NODES) ? g_bsum[t] : 0;
    sm[t] = v;
    __syncthreads();
    for (int off = 1; off < 256; off <<= 1) {
        int u = (t >= off) ? sm[t - off] : 0;
        __syncthreads();
        sm[t] += u;
        __syncthreads();
    }
    if (t < NBLK_NODES) g_boff[t] = sm[t] - v;
}

__global__ void scanC_kernel() {
    __shared__ int sm[256];
    int t = threadIdx.x;
    int i = blockIdx.x * 256 + t;
    int c = (i < N_NODES) ? g_count[i] : 0;
    sm[t] = c;
    __syncthreads();
    for (int off = 1; off < 256; off <<= 1) {
        int u = (t >= off) ? sm[t - off] : 0;
        __syncthreads();
        sm[t] += u;
        __syncthreads();
    }
    if (i < N_NODES) {
        int off = g_boff[blockIdx.x] + sm[t] - c;
        g_offs[i] = off;
        g_cursor[i] = off;
    }
}

// ---------------- scatter + edge-weight precompute (coalesced g_w) ------------
__global__ void scatter_kernel(const int* __restrict__ ei) {
    int i = blockIdx.x * blockDim.x + threadIdx.x;
    if (i >= N_EDGES / 4) return;
    int4 s4 = __ldg((const int4*)ei + i);
    int4 d4 = __ldg((const int4*)(ei + N_EDGES) + i);
    int  sv[4] = {s4.x, s4.y, s4.z, s4.w};
    int  dv[4] = {d4.x, d4.y, d4.z, d4.w};
#pragma unroll
    for (int t = 0; t < 4; t++) {
        int src = sv[t], dst = dv[t];
        int pos = atomicAdd(&g_cursor[dst], 1);
        g_esrc[pos] = src;
        float4 as = *(const float4*)(g_asrc + src * 4);
        float4 ad = *(const float4*)(g_adst + dst * 4);
        float4 w;
        w.x = __expf(leaky(as.x + ad.x));
        w.y = __expf(leaky(as.y + ad.y));
        w.z = __expf(leaky(as.z + ad.z));
        w.w = __expf(leaky(as.w + ad.w));
        g_w[pos] = w;
    }
}

// ---------------- agg: gather + head-mean + relu + fc (LDG.128 layout) --------
__global__ void agg_kernel(const float* __restrict__ bias,
                           const float* __restrict__ fc_w,
                           const float* __restrict__ fc_b,
                           float* __restrict__ out) {
    int i    = (blockIdx.x * blockDim.x + threadIdx.x) >> 5;
    int lane = threadIdx.x & 31;
    if (i >= N_NODES) return;

    const int h  = lane >> 3;
    const int cb = (lane & 7) * 8;
    const int start = g_offs[i];
    const int deg   = g_count[i];

    const float selfw = __expf(leaky(__ldg(g_asrc + 4 * i + h) + __ldg(g_adst + 4 * i + h)));
    const float* wflat = (const float*)g_w;

    float acc[8] = {0, 0, 0, 0, 0, 0, 0, 0};
    float s = 0.0f;

    int jn; float wn;
    if (deg > 0) { jn = __ldg(g_esrc + start); wn = __ldg(wflat + 4 * start + h); }
    else         { jn = i; wn = selfw; }

    for (int e = 0; e <= deg; e++) {
        int j = jn; float w = wn;
        int en = e + 1;
        if (en < deg)       { jn = __ldg(g_esrc + start + en); wn = __ldg(wflat + 4 * (start + en) + h); }
        else if (en == deg) { jn = i; wn = selfw; }

        s += w;
        uint4 v = __ldg((const uint4*)(g_xth + (size_t)j * (HC / 2)) + lane);
        float2 f0 = __half22float2(*(__half2*)&v.x);
        float2 f1 = __half22float2(*(__half2*)&v.y);
        float2 f2 = __half22float2(*(__half2*)&v.z);
        float2 f3 = __half22float2(*(__half2*)&v.w);
        acc[0] += w * f0.x; acc[1] += w * f0.y;
        acc[2] += w * f1.x; acc[3] += w * f1.y;
        acc[4] += w * f2.x; acc[5] += w * f2.y;
        acc[6] += w * f3.x; acc[7] += w * f3.y;
    }

    float inv = 0.25f / s;
#pragma unroll
    for (int c = 0; c < 8; c++) acc[c] *= inv;
#pragma unroll
    for (int c = 0; c < 8; c++) {
        acc[c] += __shfl_xor_sync(0xFFFFFFFFu, acc[c], 8);
        acc[c] += __shfl_xor_sync(0xFFFFFFFFu, acc[c], 16);
    }

    float4 b0 = __ldg((const float4*)(bias + cb));
    float4 b1 = __ldg((const float4*)(bias + cb + 4));
    float4 f0 = __ldg((const float4*)(fc_w + cb));
    float4 f1 = __ldg((const float4*)(fc_w + cb + 4));

    float p = fmaxf(acc[0] + b0.x, 0.0f) * f0.x
            + fmaxf(acc[1] + b0.y, 0.0f) * f0.y
            + fmaxf(acc[2] + b0.z, 0.0f) * f0.z
            + fmaxf(acc[3] + b0.w, 0.0f) * f0.w
            + fmaxf(acc[4] + b1.x, 0.0f) * f1.x
            + fmaxf(acc[5] + b1.y, 0.0f) * f1.y
            + fmaxf(acc[6] + b1.z, 0.0f) * f1.z
            + fmaxf(acc[7] + b1.w, 0.0f) * f1.w;

    p += __shfl_down_sync(0xFFFFFFFFu, p, 4, 8);
    p += __shfl_down_sync(0xFFFFFFFFu, p, 2, 8);
    p += __shfl_down_sync(0xFFFFFFFFu, p, 1, 8);

    if (lane == 0) out[i] = p + __ldg(fc_b);
}

// ---------------- launch ----------------
// gemm_kernel at launch index 3 (ncu capture slot) to verify the B-in-regs fix.
extern "C" void kernel_launch(void* const* d_in, const int* in_sizes, int n_in,
                              void* d_out, int out_size) {
    const float* x        = (const float*)d_in[0];
    const int*   ei       = (const int*)d_in[1];     // int32 [2, E]
    const float* W        = (const float*)d_in[2];
    const float* att_src  = (const float*)d_in[3];
    const float* att_dst  = (const float*)d_in[4];
    const float* bias     = (const float*)d_in[5];
    const float* fc_w     = (const float*)d_in[6];
    const float* fc_b     = (const float*)d_in[7];
    float*       out      = (float*)d_out;

    (void)in_sizes; (void)n_in; (void)out_size;

    prep_kernel<<<NBLK_NODES, 256>>>(W, att_src, att_dst);
    count_kernel<<<(N_EDGES / 4 + 255) / 256, 256>>>(ei);
    scanA_kernel<<<NBLK_NODES, 256>>>();
    gemm_kernel<<<NBLK_GEMM, GEMM_THREADS>>>(x);               // capture slot
    scanB_kernel<<<1, 256>>>();
    scanC_kernel<<<NBLK_NODES, 256>>>();
    scatter_kernel<<<(N_EDGES / 4 + 255) / 256, 256>>>(ei);
    agg_kernel<<<(N_NODES * 32 + 255) / 256, 256>>>(bias, fc_w, fc_b, out);
}

// round 12
// speedup vs baseline: 1.1050x; 1.0142x over previous
#include <cuda_runtime.h>
#include <cuda_fp16.h>
#include <mma.h>
#include <math_constants.h>

using namespace nvcuda;

#define N_NODES 50000
#define N_EDGES 800000
#define IN_CH   64
#define HEADS   4
#define OUT_CH  64
#define HC      (HEADS * OUT_CH)   // 256
#define NEG_SLOPE 0.2f
#define NBLK_NODES 196             // ceil(50000/256)

#define GT_M    64                 // nodes per gemm block
#define W_COLS  272                // 256 xt cols + 8 logit cols + 8 pad
#define W_LD    280                // Ws smem leading dim (halves)
#define XA_LD   72                 // x tile leading dim (halves)
#define GEMM_THREADS 288           // 9 warps
#define NBLK_GEMM ((N_NODES + GT_M - 1) / GT_M)                       // 782
#define NBLK_COUNT ((N_EDGES / 4 + GEMM_THREADS - 1) / GEMM_THREADS)  // 695

// ---------------- device scratch ----------------
__device__ __align__(16) __half2 g_xth[(size_t)N_NODES * (HC / 2)]; // [N,128] fp16x2
__device__ __align__(16) __half  g_Wh[64 * W_COLS];                 // W'' fp16
__device__ __align__(16) float g_asrc[N_NODES * HEADS];
__device__ __align__(16) float g_adst[N_NODES * HEADS];
__device__ __align__(16) float4 g_w[N_EDGES];      // per-edge softmax numerators
__device__ int   g_count[N_NODES];
__device__ int   g_offs[N_NODES];
__device__ int   g_cursor[N_NODES];
__device__ int   g_esrc[N_EDGES];
__device__ int   g_bsum[256];
__device__ int   g_boff[256];

__device__ __forceinline__ float leaky(float v) {
    return (v > 0.0f) ? v : NEG_SLOPE * v;
}

// ---------------- K0: prep — zero counts + build fp16 W'' = [W | W@Vsrc | W@Vdst | 0]
__global__ void prep_kernel(const float* __restrict__ W,
                            const float* __restrict__ att_src,
                            const float* __restrict__ att_dst) {
    int i = blockIdx.x * blockDim.x + threadIdx.x;
    if (i < N_NODES) g_count[i] = 0;
    if (i < 64 * W_COLS) {
        int k = i / W_COLS, c = i % W_COLS;
        float v;
        if (c < HC) {
            v = W[(size_t)k * HC + c];
        } else if (c < HC + 8) {
            int h = (c - HC) & 3;
            const float* av = (c < HC + 4) ? att_src : att_dst;
            float s = 0.0f;
            for (int t = 0; t < OUT_CH; t++)
                s += W[(size_t)k * HC + h * OUT_CH + t] * av[h * OUT_CH + t];
            v = s;
        } else {
            v = 0.0f;
        }
        g_Wh[i] = __float2half(v);
    }
}

// ---------------- K1 (fused): gemm blocks + count blocks in ONE launch --------
// blocks [0, NBLK_GEMM): xt = x @ W'' on fp16 HMMA (B frags register-resident).
// blocks [NBLK_GEMM, NBLK_GEMM+NBLK_COUNT): degree count (L2 atomics) — runs
// concurrently on resources the latency-bound gemm blocks leave idle.
__global__ void __launch_bounds__(GEMM_THREADS, 4)
fused_gemm_count_kernel(const float* __restrict__ x, const int* __restrict__ ei) {
    __shared__ __align__(16) __half xa[GT_M * XA_LD];      // 9216 B
    __shared__ __align__(16) __half Ws[64 * W_LD];         // 35840 B
    __shared__ __align__(16) float  stage[9][16 * 16];     // 9216 B

    // ---- count branch ----
    if (blockIdx.x >= NBLK_GEMM) {
        int i = (blockIdx.x - NBLK_GEMM) * GEMM_THREADS + threadIdx.x;
        if (i < N_EDGES / 4) {
            int4 d = __ldg((const int4*)(ei + N_EDGES) + i);
            atomicAdd(&g_count[d.x], 1);
            atomicAdd(&g_count[d.y], 1);
            atomicAdd(&g_count[d.z], 1);
            atomicAdd(&g_count[d.w], 1);
        }
        return;
    }

    // ---- gemm branch ----
    const int tid  = threadIdx.x;
    const int warp = tid >> 5;
    const int lane = tid & 31;
    const int nblk = blockIdx.x * GT_M;

    for (int i = tid; i < GT_M * IN_CH; i += GEMM_THREADS) {
        int n = i >> 6, k = i & 63;
        int node = nblk + n;
        xa[n * XA_LD + k] = __float2half((node < N_NODES) ? x[(size_t)node * IN_CH + k] : 0.0f);
    }
    for (int i = tid; i < 64 * (W_COLS / 8); i += GEMM_THREADS) {
        int k = i / (W_COLS / 8), c8 = i % (W_COLS / 8);
        *(uint4*)(Ws + k * W_LD + c8 * 8) = __ldg((const uint4*)(g_Wh + k * W_COLS) + c8);
    }
    __syncthreads();

    const int  ct0  = (warp < 8) ? (2 * warp) : 16;
    const bool has2 = (warp < 8);
    const int  ct1  = ct0 + 1;

    wmma::fragment<wmma::matrix_b, 16, 16, 16, __half, wmma::row_major> b0[4], b1[4];
#pragma unroll
    for (int kk = 0; kk < 4; kk++) {
        wmma::load_matrix_sync(b0[kk], Ws + (kk * 16) * W_LD + ct0 * 16, W_LD);
        if (has2) wmma::load_matrix_sync(b1[kk], Ws + (kk * 16) * W_LD + ct1 * 16, W_LD);
    }

    float* st = stage[warp];
    __half* xth = (__half*)g_xth;

    auto emit = [&](int nt, int ct, wmma::fragment<wmma::accumulator, 16, 16, 16, float>& acc) {
        wmma::store_matrix_sync(st, acc, 16, wmma::mem_row_major);
        __syncwarp();
        if (ct < 16) {
            int row = lane & 15, ch = lane >> 4;
            int node = nblk + nt * 16 + row;
            if (node < N_NODES) {
                float4 u = *(const float4*)(st + row * 16 + ch * 8);
                float4 v = *(const float4*)(st + row * 16 + ch * 8 + 4);
                __half2 h0 = __floats2half2_rn(u.x, u.y);
                __half2 h1 = __floats2half2_rn(u.z, u.w);
                __half2 h2 = __floats2half2_rn(v.x, v.y);
                __half2 h3 = __floats2half2_rn(v.z, v.w);
                uint4 o = make_uint4(*(unsigned*)&h0, *(unsigned*)&h1,
                                     *(unsigned*)&h2, *(unsigned*)&h3);
                *(uint4*)(xth + (size_t)node * HC + ct * 16 + ch * 8) = o;
            }
        } else {
            if (lane < 16) {
                int node = nblk + nt * 16 + lane;
                if (node < N_NODES) {
                    *(float4*)(g_asrc + node * 4) = *(const float4*)(st + lane * 16);
                    *(float4*)(g_adst + node * 4) = *(const float4*)(st + lane * 16 + 4);
                }
            }
        }
        __syncwarp();
    };

#pragma unroll
    for (int nt = 0; nt < 4; nt++) {
        wmma::fragment<wmma::matrix_a, 16, 16, 16, __half, wmma::row_major> af;
        wmma::fragment<wmma::accumulator, 16, 16, 16, float> acc0, acc1;
        wmma::fill_fragment(acc0, 0.0f);
        if (has2) wmma::fill_fragment(acc1, 0.0f);
#pragma unroll
        for (int kk = 0; kk < 4; kk++) {
            wmma::load_matrix_sync(af, xa + (nt * 16) * XA_LD + kk * 16, XA_LD);
            wmma::mma_sync(acc0, af, b0[kk], acc0);
            if (has2) wmma::mma_sync(acc1, af, b1[kk], acc1);
        }
        emit(nt, ct0, acc0);
        if (has2) emit(nt, ct1, acc1);
    }
}

// ---------------- CSR scans ----------------
__global__ void scanA_kernel() {
    __shared__ int wsum[8];
    int i = blockIdx.x * 256 + threadIdx.x;
    int c = (i < N_NODES) ? g_count[i] : 0;
    int v = c;
#pragma unroll
    for (int off = 16; off > 0; off >>= 1)
        v += __shfl_down_sync(0xFFFFFFFFu, v, off);
    if ((threadIdx.x & 31) == 0) wsum[threadIdx.x >> 5] = v;
    __syncthreads();
    if (threadIdx.x == 0) {
        int s = 0;
#pragma unroll
        for (int w = 0; w < 8; w++) s += wsum[w];
        g_bsum[blockIdx.x] = s;
    }
}

__global__ void scanB_kernel() {
    __shared__ int sm[256];
    int t = threadIdx.x;
    int v = (t < NBLK_NODES) ? g_bsum[t] : 0;
    sm[t] = v;
    __syncthreads();
    for (int off = 1; off < 256; off <<= 1) {
        int u = (t >= off) ? sm[t - off] : 0;
        __syncthreads();
        sm[t] += u;
        __syncthreads();
    }
    if (t < NBLK_NODES) g_boff[t] = sm[t] - v;
}

__global__ void scanC_kernel() {
    __shared__ int sm[256];
    int t = threadIdx.x;
    int i = blockIdx.x * 256 + t;
    int c = (i < N_NODES) ? g_count[i] : 0;
    sm[t] = c;
    __syncthreads();
    for (int off = 1; off < 256; off <<= 1) {
        int u = (t >= off) ? sm[t - off] : 0;
        __syncthreads();
        sm[t] += u;
        __syncthreads();
    }
    if (i < N_NODES) {
        int off = g_boff[blockIdx.x] + sm[t] - c;
        g_offs[i] = off;
        g_cursor[i] = off;
    }
}

// ---------------- scatter + edge-weight precompute (coalesced g_w) ------------
__global__ void scatter_kernel(const int* __restrict__ ei) {
    int i = blockIdx.x * blockDim.x + threadIdx.x;
    if (i >= N_EDGES / 4) return;
    int4 s4 = __ldg((const int4*)ei + i);
    int4 d4 = __ldg((const int4*)(ei + N_EDGES) + i);
    int  sv[4] = {s4.x, s4.y, s4.z, s4.w};
    int  dv[4] = {d4.x, d4.y, d4.z, d4.w};
#pragma unroll
    for (int t = 0; t < 4; t++) {
        int src = sv[t], dst = dv[t];
        int pos = atomicAdd(&g_cursor[dst], 1);
        g_esrc[pos] = src;
        float4 as = *(const float4*)(g_asrc + src * 4);
        float4 ad = *(const float4*)(g_adst + dst * 4);
        float4 w;
        w.x = __expf(leaky(as.x + ad.x));
        w.y = __expf(leaky(as.y + ad.y));
        w.z = __expf(leaky(as.z + ad.z));
        w.w = __expf(leaky(as.w + ad.w));
        g_w[pos] = w;
    }
}

// ---------------- agg: gather + head-mean + relu + fc (LDG.128 layout) --------
__global__ void agg_kernel(const float* __restrict__ bias,
                           const float* __restrict__ fc_w,
                           const float* __restrict__ fc_b,
                           float* __restrict__ out) {
    int i    = (blockIdx.x * blockDim.x + threadIdx.x) >> 5;
    int lane = threadIdx.x & 31;
    if (i >= N_NODES) return;

    const int h  = lane >> 3;
    const int cb = (lane & 7) * 8;
    const int start = g_offs[i];
    const int deg   = g_count[i];

    const float selfw = __expf(leaky(__ldg(g_asrc + 4 * i + h) + __ldg(g_adst + 4 * i + h)));
    const float* wflat = (const float*)g_w;

    float acc[8] = {0, 0, 0, 0, 0, 0, 0, 0};
    float s = 0.0f;

    int jn; float wn;
    if (deg > 0) { jn = __ldg(g_esrc + start); wn = __ldg(wflat + 4 * start + h); }
    else         { jn = i; wn = selfw; }

    for (int e = 0; e <= deg; e++) {
        int j = jn; float w = wn;
        int en = e + 1;
        if (en < deg)       { jn = __ldg(g_esrc + start + en); wn = __ldg(wflat + 4 * (start + en) + h); }
        else if (en == deg) { jn = i; wn = selfw; }

        s += w;
        uint4 v = __ldg((const uint4*)(g_xth + (size_t)j * (HC / 2)) + lane);
        float2 f0 = __half22float2(*(__half2*)&v.x);
        float2 f1 = __half22float2(*(__half2*)&v.y);
        float2 f2 = __half22float2(*(__half2*)&v.z);
        float2 f3 = __half22float2(*(__half2*)&v.w);
        acc[0] += w * f0.x; acc[1] += w * f0.y;
        acc[2] += w * f1.x; acc[3] += w * f1.y;
        acc[4] += w * f2.x; acc[5] += w * f2.y;
        acc[6] += w * f3.x; acc[7] += w * f3.y;
    }

    float inv = 0.25f / s;
#pragma unroll
    for (int c = 0; c < 8; c++) acc[c] *= inv;
#pragma unroll
    for (int c = 0; c < 8; c++) {
        acc[c] += __shfl_xor_sync(0xFFFFFFFFu, acc[c], 8);
        acc[c] += __shfl_xor_sync(0xFFFFFFFFu, acc[c], 16);
    }

    float4 b0 = __ldg((const float4*)(bias + cb));
    float4 b1 = __ldg((const float4*)(bias + cb + 4));
    float4 f0 = __ldg((const float4*)(fc_w + cb));
    float4 f1 = __ldg((const float4*)(fc_w + cb + 4));

    float p = fmaxf(acc[0] + b0.x, 0.0f) * f0.x
            + fmaxf(acc[1] + b0.y, 0.0f) * f0.y
            + fmaxf(acc[2] + b0.z, 0.0f) * f0.z
            + fmaxf(acc[3] + b0.w, 0.0f) * f0.w
            + fmaxf(acc[4] + b1.x, 0.0f) * f1.x
            + fmaxf(acc[5] + b1.y, 0.0f) * f1.y
            + fmaxf(acc[6] + b1.z, 0.0f) * f1.z
            + fmaxf(acc[7] + b1.w, 0.0f) * f1.w;

    p += __shfl_down_sync(0xFFFFFFFFu, p, 4, 8);
    p += __shfl_down_sync(0xFFFFFFFFu, p, 2, 8);
    p += __shfl_down_sync(0xFFFFFFFFu, p, 1, 8);

    if (lane == 0) out[i] = p + __ldg(fc_b);
}

// ---------------- launch ----------------
extern "C" void kernel_launch(void* const* d_in, const int* in_sizes, int n_in,
                              void* d_out, int out_size) {
    const float* x        = (const float*)d_in[0];
    const int*   ei       = (const int*)d_in[1];     // int32 [2, E]
    const float* W        = (const float*)d_in[2];
    const float* att_src  = (const float*)d_in[3];
    const float* att_dst  = (const float*)d_in[4];
    const float* bias     = (const float*)d_in[5];
    const float* fc_w     = (const float*)d_in[6];
    const float* fc_b     = (const float*)d_in[7];
    float*       out      = (float*)d_out;

    (void)in_sizes; (void)n_in; (void)out_size;

    prep_kernel<<<NBLK_NODES, 256>>>(W, att_src, att_dst);
    fused_gemm_count_kernel<<<NBLK_GEMM + NBLK_COUNT, GEMM_THREADS>>>(x, ei);
    scanA_kernel<<<NBLK_NODES, 256>>>();
    scanB_kernel<<<1, 256>>>();
    scanC_kernel<<<NBLK_NODES, 256>>>();
    scatter_kernel<<<(N_EDGES / 4 + 255) / 256, 256>>>(ei);
    agg_kernel<<<(N_NODES * 32 + 255) / 256, 256>>>(bias, fc_w, fc_b, out);
}